// round 4
// baseline (speedup 1.0000x reference)
#include <cuda_runtime.h>

// KohonenSOM cdist: out[b][n] = || x[b] - w[n] ||_2
// x: [B=65536, 32] fp32, w: [N=4900, 32] fp32, out: [B, N] fp32.
// Expansion: sqrt(max(x2[b] + w2[n] - 2*<x[b],w[n]>, 0)).
//
// SGEMM-style: 128x128 block tile, 8x8 per-thread register tile, K=32 loaded
// once into transposed padded smem (conflict-free LDS.128 in compute loop).

constexpr int TM = 128;
constexpr int TN = 128;
constexpr int TK = 32;

__device__ __forceinline__ float fdist(float x2, float w2, float c) {
    float sq = fmaxf(fmaf(-2.0f, c, x2 + w2), 0.0f);
    float r;
    asm("sqrt.approx.f32 %0, %1;" : "=f"(r) : "f"(sq));
    return r;
}

__global__ __launch_bounds__(256, 2)
void som_cdist_kernel(const float* __restrict__ X, const float* __restrict__ W,
                      float* __restrict__ out, int B, int N) {
    __shared__ float xs[TK][TM + 4];   // transposed: xs[k][m], padded stride 132
    __shared__ float ws[TK][TN + 4];   // transposed: ws[k][n]
    __shared__ float xn[TM];
    __shared__ float wn[TN];

    const int tid = threadIdx.x;
    const int bm  = blockIdx.x * TM;   // batch-row offset
    const int bn  = blockIdx.y * TN;   // neuron-col offset

    // ---- one-shot tile load (K=32 total, no k-pipeline needed) ----
    {
        const float4* xg = reinterpret_cast<const float4*>(X);
        const float4* wg = reinterpret_cast<const float4*>(W);
        #pragma unroll
        for (int i = 0; i < 4; i++) {
            int idx = tid + i * 256;          // 0..1023 float4 slots
            int row = idx >> 3;               // tile row
            int k4  = idx & 7;                // which float4 along K

            int gm = bm + row;
            float4 vx = make_float4(0.f, 0.f, 0.f, 0.f);
            if (gm < B) vx = xg[(size_t)gm * 8 + k4];
            xs[k4 * 4 + 0][row] = vx.x;
            xs[k4 * 4 + 1][row] = vx.y;
            xs[k4 * 4 + 2][row] = vx.z;
            xs[k4 * 4 + 3][row] = vx.w;

            int gn = bn + row;
            float4 vw = make_float4(0.f, 0.f, 0.f, 0.f);
            if (gn < N) vw = wg[(size_t)gn * 8 + k4];
            ws[k4 * 4 + 0][row] = vw.x;
            ws[k4 * 4 + 1][row] = vw.y;
            ws[k4 * 4 + 2][row] = vw.z;
            ws[k4 * 4 + 3][row] = vw.w;
        }
    }
    __syncthreads();

    // ---- row/col squared norms (conflict-free: bank = (4k + m) varies) ----
    if (tid < TM) {
        float s = 0.f;
        #pragma unroll
        for (int k = 0; k < TK; k++) { float v = xs[k][tid]; s = fmaf(v, v, s); }
        xn[tid] = s;
    } else {
        int r = tid - TM;
        float s = 0.f;
        #pragma unroll
        for (int k = 0; k < TK; k++) { float v = ws[k][r]; s = fmaf(v, v, s); }
        wn[r] = s;
    }
    __syncthreads();

    // ---- 8x8 register-tile cross-product accumulation ----
    const int tx = tid & 15;           // n direction (16)
    const int ty = tid >> 4;           // m direction (16)
    const int m0 = ty * 8;
    const int n0 = tx * 4;             // cols n0..n0+3 and n0+64..n0+67

    float acc[8][8];
    #pragma unroll
    for (int i = 0; i < 8; i++)
        #pragma unroll
        for (int j = 0; j < 8; j++) acc[i][j] = 0.f;

    #pragma unroll 8
    for (int k = 0; k < TK; k++) {
        float xv[8], wv[8];
        *reinterpret_cast<float4*>(&xv[0]) = *reinterpret_cast<const float4*>(&xs[k][m0]);
        *reinterpret_cast<float4*>(&xv[4]) = *reinterpret_cast<const float4*>(&xs[k][m0 + 4]);
        *reinterpret_cast<float4*>(&wv[0]) = *reinterpret_cast<const float4*>(&ws[k][n0]);
        *reinterpret_cast<float4*>(&wv[4]) = *reinterpret_cast<const float4*>(&ws[k][n0 + 64]);
        #pragma unroll
        for (int i = 0; i < 8; i++)
            #pragma unroll
            for (int j = 0; j < 8; j++)
                acc[i][j] = fmaf(xv[i], wv[j], acc[i][j]);
    }

    // ---- epilogue: combine norms, sqrt, store ----
    float xnr[8], wnr[8];
    #pragma unroll
    for (int i = 0; i < 8; i++) xnr[i] = xn[m0 + i];
    #pragma unroll
    for (int j = 0; j < 4; j++) { wnr[j] = wn[n0 + j]; wnr[4 + j] = wn[n0 + 64 + j]; }

    const bool full_n = (bn + TN) <= N;

    #pragma unroll
    for (int i = 0; i < 8; i++) {
        int gm = bm + m0 + i;
        if (gm >= B) break;
        size_t rowoff = (size_t)gm * (size_t)N;

        float d0[4], d1[4];
        #pragma unroll
        for (int j = 0; j < 4; j++) {
            d0[j] = fdist(xnr[i], wnr[j],     acc[i][j]);
            d1[j] = fdist(xnr[i], wnr[4 + j], acc[i][4 + j]);
        }

        if (full_n) {
            // bn, n0 multiples of 4 and N%4==0 -> 16B-aligned vector stores
            *reinterpret_cast<float4*>(out + rowoff + bn + n0) =
                make_float4(d0[0], d0[1], d0[2], d0[3]);
            *reinterpret_cast<float4*>(out + rowoff + bn + n0 + 64) =
                make_float4(d1[0], d1[1], d1[2], d1[3]);
        } else {
            #pragma unroll
            for (int j = 0; j < 4; j++) {
                int gn0 = bn + n0 + j;
                int gn1 = bn + n0 + 64 + j;
                if (gn0 < N) out[rowoff + gn0] = d0[j];
                if (gn1 < N) out[rowoff + gn1] = d1[j];
            }
        }
    }
}

extern "C" void kernel_launch(void* const* d_in, const int* in_sizes, int n_in,
                              void* d_out, int out_size) {
    const float* X = (const float*)d_in[0];     // [B, 32]
    const float* W = (const float*)d_in[1];     // [N, 32]
    float* out = (float*)d_out;

    const int B = in_sizes[0] / 32;
    const int N = in_sizes[1] / 32;

    dim3 grid((B + TM - 1) / TM, (N + TN - 1) / TN);
    som_cdist_kernel<<<grid, 256>>>(X, W, out, B, N);
}

// round 7
// speedup vs baseline: 1.2035x; 1.2035x over previous
#include <cuda_runtime.h>

// KohonenSOM cdist: out[b][n] = || x[b] - w[n] ||_2
// x: [B=65536, 32] fp32, w: [N=4900, 32] fp32, out: [B, N] fp32.
// sqrt(max(x2[b] + w2[n] - 2*<x[b],w[n]>, 0)).
//
// R4: packed fp32 math via Blackwell fma.rn.f32x2 (FFMA2). 8x8 register tile
// becomes 8 (m broadcast) x 4 (n f32x2 pairs): 32 FFMA2/k instead of 64 FFMA/k.
// n-pairs load pre-packed from shared (ulonglong2, 16B aligned); m broadcasts
// packed with mov.b64 {v,v} on the alu pipe (overlaps fma pipe).

constexpr int TM = 128;
constexpr int TN = 128;
constexpr int TK = 32;

typedef unsigned long long u64;

__device__ __forceinline__ u64 fma2(u64 a, u64 b, u64 c) {
    u64 d;
    asm("fma.rn.f32x2 %0, %1, %2, %3;" : "=l"(d) : "l"(a), "l"(b), "l"(c));
    return d;
}
__device__ __forceinline__ u64 add2(u64 a, u64 b) {
    u64 d;
    asm("add.rn.f32x2 %0, %1, %2;" : "=l"(d) : "l"(a), "l"(b));
    return d;
}
__device__ __forceinline__ u64 bcast2(float v) {
    u64 r;
    asm("mov.b64 %0, {%1, %1};" : "=l"(r) : "f"(v));
    return r;
}
__device__ __forceinline__ void unpack2(float& lo, float& hi, u64 v) {
    asm("mov.b64 {%0, %1}, %2;" : "=f"(lo), "=f"(hi) : "l"(v));
}
__device__ __forceinline__ float fsqrt_approx(float sq) {
    float r;
    asm("sqrt.approx.f32 %0, %1;" : "=f"(r) : "f"(sq));
    return r;
}

__global__ __launch_bounds__(256, 2)
void som_cdist_kernel(const float* __restrict__ X, const float* __restrict__ W,
                      float* __restrict__ out, int B, int N) {
    __shared__ float xs[TK][TM + 4];   // transposed: xs[k][m], padded stride 132
    __shared__ float ws[TK][TN + 4];   // transposed: ws[k][n]
    __shared__ float xn[TM];
    __shared__ float wn[TN];

    const int tid = threadIdx.x;
    const int bm  = blockIdx.x * TM;
    const int bn  = blockIdx.y * TN;

    // ---- one-shot tile load (K=32, no k-pipeline) ----
    {
        const float4* xg = reinterpret_cast<const float4*>(X);
        const float4* wg = reinterpret_cast<const float4*>(W);
        #pragma unroll
        for (int i = 0; i < 4; i++) {
            int idx = tid + i * 256;
            int row = idx >> 3;
            int k4  = idx & 7;

            int gm = bm + row;
            float4 vx = make_float4(0.f, 0.f, 0.f, 0.f);
            if (gm < B) vx = xg[(size_t)gm * 8 + k4];
            xs[k4 * 4 + 0][row] = vx.x;
            xs[k4 * 4 + 1][row] = vx.y;
            xs[k4 * 4 + 2][row] = vx.z;
            xs[k4 * 4 + 3][row] = vx.w;

            int gn = bn + row;
            float4 vw = make_float4(0.f, 0.f, 0.f, 0.f);
            if (gn < N) vw = wg[(size_t)gn * 8 + k4];
            ws[k4 * 4 + 0][row] = vw.x;
            ws[k4 * 4 + 1][row] = vw.y;
            ws[k4 * 4 + 2][row] = vw.z;
            ws[k4 * 4 + 3][row] = vw.w;
        }
    }
    __syncthreads();

    // ---- row/col squared norms ----
    if (tid < TM) {
        float s = 0.f;
        #pragma unroll
        for (int k = 0; k < TK; k++) { float v = xs[k][tid]; s = fmaf(v, v, s); }
        xn[tid] = s;
    } else {
        int r = tid - TM;
        float s = 0.f;
        #pragma unroll
        for (int k = 0; k < TK; k++) { float v = ws[k][r]; s = fmaf(v, v, s); }
        wn[r] = s;
    }
    __syncthreads();

    // ---- packed 8x(4 pair) register-tile accumulation ----
    const int tx = tid & 15;           // n direction (16)
    const int ty = tid >> 4;           // m direction (16)
    const int m0 = ty * 8;
    const int n0 = tx * 4;             // cols n0..n0+3 and n0+64..n0+67

    u64 acc[8][4];                     // [m][n-pair]; pairs 0,1 = n0..n0+3; 2,3 = n0+64..n0+67
    #pragma unroll
    for (int i = 0; i < 8; i++)
        #pragma unroll
        for (int j = 0; j < 4; j++) acc[i][j] = 0ull;

    #pragma unroll 8
    for (int k = 0; k < TK; k++) {
        // n-pairs: already contiguous in shared -> load packed (16B aligned)
        u64 wp[4];
        {
            ulonglong2 a = *reinterpret_cast<const ulonglong2*>(&ws[k][n0]);
            ulonglong2 b = *reinterpret_cast<const ulonglong2*>(&ws[k][n0 + 64]);
            wp[0] = a.x; wp[1] = a.y; wp[2] = b.x; wp[3] = b.y;
        }
        // m broadcasts: load float4s, duplicate into 64-bit pairs (alu pipe)
        float xa[8];
        *reinterpret_cast<float4*>(&xa[0]) = *reinterpret_cast<const float4*>(&xs[k][m0]);
        *reinterpret_cast<float4*>(&xa[4]) = *reinterpret_cast<const float4*>(&xs[k][m0 + 4]);
        u64 xp[8];
        #pragma unroll
        for (int i = 0; i < 8; i++) xp[i] = bcast2(xa[i]);

        #pragma unroll
        for (int i = 0; i < 8; i++)
            #pragma unroll
            for (int j = 0; j < 4; j++)
                acc[i][j] = fma2(xp[i], wp[j], acc[i][j]);
    }

    // ---- epilogue: sq = x2 + w2 - 2c (packed), then scalar max+sqrt ----
    u64 w2p[4];
    {
        ulonglong2 a = *reinterpret_cast<const ulonglong2*>(&wn[n0]);
        ulonglong2 b = *reinterpret_cast<const ulonglong2*>(&wn[n0 + 64]);
        w2p[0] = a.x; w2p[1] = a.y; w2p[2] = b.x; w2p[3] = b.y;
    }
    const u64 neg2 = bcast2(-2.0f);
    const bool full_n = (bn + TN) <= N;

    #pragma unroll
    for (int i = 0; i < 8; i++) {
        int gm = bm + m0 + i;
        if (gm >= B) break;
        size_t rowoff = (size_t)gm * (size_t)N;

        u64 x2p = bcast2(xn[m0 + i]);
        float d[8];
        #pragma unroll
        for (int j = 0; j < 4; j++) {
            u64 s  = add2(x2p, w2p[j]);
            u64 sq = fma2(neg2, acc[i][j], s);
            float lo, hi;
            unpack2(lo, hi, sq);
            d[j * 2 + 0] = fsqrt_approx(fmaxf(lo, 0.0f));
            d[j * 2 + 1] = fsqrt_approx(fmaxf(hi, 0.0f));
        }

        if (full_n) {
            *reinterpret_cast<float4*>(out + rowoff + bn + n0) =
                make_float4(d[0], d[1], d[2], d[3]);
            *reinterpret_cast<float4*>(out + rowoff + bn + n0 + 64) =
                make_float4(d[4], d[5], d[6], d[7]);
        } else {
            #pragma unroll
            for (int j = 0; j < 4; j++) {
                int gn0 = bn + n0 + j;
                int gn1 = bn + n0 + 64 + j;
                if (gn0 < N) out[rowoff + gn0] = d[j];
                if (gn1 < N) out[rowoff + gn1] = d[4 + j];
            }
        }
    }
}

extern "C" void kernel_launch(void* const* d_in, const int* in_sizes, int n_in,
                              void* d_out, int out_size) {
    const float* X = (const float*)d_in[0];     // [B, 32]
    const float* W = (const float*)d_in[1];     // [N, 32]
    float* out = (float*)d_out;

    const int B = in_sizes[0] / 32;
    const int N = in_sizes[1] / 32;

    dim3 grid((B + TM - 1) / TM, (N + TN - 1) / TN);
    som_cdist_kernel<<<grid, 256>>>(X, W, out, B, N);
}

// round 11
// speedup vs baseline: 1.2160x; 1.0104x over previous
#include <cuda_runtime.h>
#include <cuda_bf16.h>
#include <stdint.h>

// KohonenSOM cdist via warp-level bf16-split HMMA (mma.sync, plain sm_103 ISA).
// out[b][n] = sqrt(max(x2[b] + w2[n] - 2*<x[b],w[n]>, 0))
// Cross term: fp32 -> bf16 hi+lo, 3 accumulated passes (hh + hl + lh) on
// mma.sync.m16n8k16.f32.bf16.bf16.f32. Norms exact fp32. 128x128 block tile,
// 8 warps (2x4), 64x32 warp tile. SW128-swizzled smem, ldmatrix fragments.

#define TM 128
#define TN 128

#define SW128(o) ((o) ^ (((o) >> 3) & 0x70))

static __device__ __forceinline__ uint32_t smem_u32(const void* p) {
    uint32_t a;
    asm("{ .reg .u64 t; cvta.to.shared.u64 t, %1; cvt.u32.u64 %0, t; }"
        : "=r"(a) : "l"(p));
    return a;
}
static __device__ __forceinline__ float fsqrt_approx(float sq) {
    float r;
    asm("sqrt.approx.f32 %0, %1;" : "=f"(r) : "f"(sq));
    return r;
}
static __device__ __forceinline__ float fdist(float x2, float w2, float c) {
    return fsqrt_approx(fmaxf(fmaf(-2.0f, c, x2 + w2), 0.0f));
}
static __device__ __forceinline__ uint32_t pack_bf16x2(float lo, float hi) {
    uint32_t r;
    asm("cvt.rn.satfinite.bf16x2.f32 %0, %1, %2;" : "=r"(r) : "f"(hi), "f"(lo));
    return r;
}
#define LDSM_X4(r0, r1, r2, r3, addr)                                   \
    asm volatile("ldmatrix.sync.aligned.m8n8.x4.shared.b16 "            \
                 "{%0, %1, %2, %3}, [%4];"                              \
                 : "=r"(r0), "=r"(r1), "=r"(r2), "=r"(r3) : "r"(addr))
#define MMA_16816(c, a, b)                                              \
    asm volatile("mma.sync.aligned.m16n8k16.row.col.f32.bf16.bf16.f32 " \
                 "{%0, %1, %2, %3}, {%4, %5, %6, %7}, {%8, %9}, "       \
                 "{%0, %1, %2, %3};"                                    \
                 : "+f"((c)[0]), "+f"((c)[1]), "+f"((c)[2]), "+f"((c)[3]) \
                 : "r"((a)[0]), "r"((a)[1]), "r"((a)[2]), "r"((a)[3]),  \
                   "r"((b)[0]), "r"((b)[1]))

__global__ __launch_bounds__(256, 2)
void som_cdist_hmma(const float* __restrict__ X, const float* __restrict__ W,
                    float* __restrict__ out, int B, int N) {
    // Row layout (128 B): bytes [0,64) = hi plane (bf16 k=0..31),
    //                     bytes [64,128) = lo plane. SW128-swizzled.
    __shared__ alignas(1024) __nv_bfloat16 As[128 * 64];
    __shared__ alignas(1024) __nv_bfloat16 Bs[128 * 64];
    __shared__ float xns[TM];
    __shared__ float wns[TN];

    const int tid  = threadIdx.x;
    const int lane = tid & 31;
    const int wid  = tid >> 5;
    const int bm   = blockIdx.x * TM;
    const int bn   = blockIdx.y * TN;

    // ---- load fp32 rows, split to bf16 hi/lo, swizzled STS, fp32 norms ----
    {
        const int  row = tid & 127;
        const bool isx = tid < 128;
        const int  rot = (row >> 3) & 3;   // stagger float4 index to spread banks

        float vals[32];
        {
            const float4* g;
            bool ok;
            if (isx) { int gm = bm + row; ok = gm < B; g = reinterpret_cast<const float4*>(X) + (size_t)gm * 8; }
            else     { int gn = bn + row; ok = gn < N; g = reinterpret_cast<const float4*>(W) + (size_t)gn * 8; }
            if (ok) {
                #pragma unroll
                for (int j = 0; j < 8; j++)
                    *reinterpret_cast<float4*>(&vals[4 * j]) = g[(j + rot) & 7];
            } else {
                #pragma unroll
                for (int k = 0; k < 32; k++) vals[k] = 0.f;
            }
        }

        float s = 0.f;
        #pragma unroll
        for (int k = 0; k < 32; k++) s = fmaf(vals[k], vals[k], s);

        char* base = (char*)(isx ? (void*)As : (void*)Bs);
        const uint32_t rb = (uint32_t)row * 128u;
        #pragma unroll
        for (int p = 0; p < 16; p++) {
            float a = vals[2 * p], b = vals[2 * p + 1];
            uint32_t hp = pack_bf16x2(a, b);
            float ra = a - __uint_as_float(hp << 16);
            float rb2 = b - __uint_as_float(hp & 0xFFFF0000u);
            uint32_t lp = pack_bf16x2(ra, rb2);
            // original pair index (rotation compensated)
            uint32_t q4 = (uint32_t)(((p + 2 * rot) & 15) * 4);
            *reinterpret_cast<uint32_t*>(base + SW128(rb + q4))      = hp;  // hi
            *reinterpret_cast<uint32_t*>(base + SW128(rb + 64 + q4)) = lp;  // lo
        }
        if (isx) xns[row] = s; else wns[row] = s;
    }
    __syncthreads();

    // ---- warp-MMA mainloop: 3 passes x 2 k16-steps x (4m x 4n) atoms ----
    const int wm  = wid & 1;          // 64-row half
    const int wn4 = wid >> 1;         // 32-col quarter
    const uint32_t asb = smem_u32(As);
    const uint32_t bsb = smem_u32(Bs);

    // ldmatrix per-thread address components
    const int a_row = (lane & 7) + (lane & 8);              // 0..15
    const int a_k16 = ((lane >> 4) & 1) * 16;               // byte sel within k16
    const int b_row = (lane & 7) + ((lane >> 4) & 1) * 8;   // n within 16
    const int b_k16 = ((lane >> 3) & 1) * 16;

    float acc[4][4][4];
    #pragma unroll
    for (int mi = 0; mi < 4; mi++)
        #pragma unroll
        for (int nt = 0; nt < 4; nt++)
            #pragma unroll
            for (int c = 0; c < 4; c++) acc[mi][nt][c] = 0.f;

    #pragma unroll
    for (int pass = 0; pass < 3; pass++) {
        const int hiA = (pass == 2) ? 64 : 0;   // pass2: A-lo
        const int hiB = (pass == 1) ? 64 : 0;   // pass1: B-lo
        #pragma unroll
        for (int ks = 0; ks < 2; ks++) {
            const int koffA = hiA + ks * 32 + a_k16;
            const int koffB = hiB + ks * 32 + b_k16;

            uint32_t afr[4][4];
            #pragma unroll
            for (int mi = 0; mi < 4; mi++) {
                int m = wm * 64 + mi * 16 + a_row;
                uint32_t ad = asb + SW128((uint32_t)(m * 128 + koffA));
                LDSM_X4(afr[mi][0], afr[mi][1], afr[mi][2], afr[mi][3], ad);
            }
            uint32_t bfr[4][2];
            #pragma unroll
            for (int pr = 0; pr < 2; pr++) {
                int n = wn4 * 32 + pr * 16 + b_row;
                uint32_t bd = bsb + SW128((uint32_t)(n * 128 + koffB));
                uint32_t r0, r1, r2, r3;
                LDSM_X4(r0, r1, r2, r3, bd);
                bfr[2 * pr][0] = r0;  bfr[2 * pr][1] = r1;
                bfr[2 * pr + 1][0] = r2;  bfr[2 * pr + 1][1] = r3;
            }
            #pragma unroll
            for (int mi = 0; mi < 4; mi++)
                #pragma unroll
                for (int nt = 0; nt < 4; nt++)
                    MMA_16816(acc[mi][nt], afr[mi], bfr[nt]);
        }
    }

    // ---- epilogue: combine norms, sqrt, coalesced float2 stores ----
    const int tg = lane >> 2;   // row within atom (0..7)
    const int tq = lane & 3;    // col pair

    #pragma unroll
    for (int mi = 0; mi < 4; mi++) {
        int ml0 = wm * 64 + mi * 16 + tg;
        float x2a = xns[ml0];
        float x2b = xns[ml0 + 8];
        int gm0 = bm + ml0;
        if (gm0 >= B) continue;
        float* r0p = out + (size_t)gm0 * (size_t)N;
        float* r1p = out + (size_t)(gm0 + 8) * (size_t)N;

        #pragma unroll
        for (int nt = 0; nt < 4; nt++) {
            int nl = wn4 * 32 + nt * 8 + tq * 2;
            int gn = bn + nl;
            if (gn < N) {
                float w20 = wns[nl], w21 = wns[nl + 1];
                float2 o0, o1;
                o0.x = fdist(x2a, w20, acc[mi][nt][0]);
                o0.y = fdist(x2a, w21, acc[mi][nt][1]);
                o1.x = fdist(x2b, w20, acc[mi][nt][2]);
                o1.y = fdist(x2b, w21, acc[mi][nt][3]);
                *reinterpret_cast<float2*>(r0p + gn) = o0;
                if (gm0 + 8 < B)
                    *reinterpret_cast<float2*>(r1p + gn) = o1;
            }
        }
    }
}

extern "C" void kernel_launch(void* const* d_in, const int* in_sizes, int n_in,
                              void* d_out, int out_size) {
    const float* X = (const float*)d_in[0];     // [B, 32]
    const float* W = (const float*)d_in[1];     // [N, 32]
    float* out = (float*)d_out;

    const int B = in_sizes[0] / 32;
    const int N = in_sizes[1] / 32;

    dim3 grid((B + TM - 1) / TM, (N + TN - 1) / TN);
    som_cdist_hmma<<<grid, 256>>>(X, W, out, B, N);
}